// round 7
// baseline (speedup 1.0000x reference)
#include <cuda_runtime.h>
#include <cuda_bf16.h>
#include <math.h>
#include <string.h>

// Problem constants (fixed by the dataset)
#define TT 1024
#define SS 512
#define DD 32
#define KK 64
#define LOG2PI 1.8378770664093453f
#define A_TILE 64   // (t,s) pairs per emission block

// Device-global scratch (no allocations allowed)
__device__ float2 g_pp[KK * DD];                 // (-0.5/covar, mean/covar)
__device__ float  g_base[KK];                    // log-density constant per state
__device__ float  g_logden[SS];                  // per-sequence sum log(denom)
__device__ float  g_probs[(size_t)SS * TT * KK]; // emission probs, [s][t][k]

// ---- packed fp32x2 helpers (sm_103a) --------------------------------------
__device__ __forceinline__ unsigned long long ffma2(unsigned long long a,
                                                    unsigned long long b,
                                                    unsigned long long c) {
    unsigned long long d;
    asm("fma.rn.f32x2 %0, %1, %2, %3;" : "=l"(d) : "l"(a), "l"(b), "l"(c));
    return d;
}
__device__ __forceinline__ unsigned long long fadd2(unsigned long long a,
                                                    unsigned long long b) {
    unsigned long long d;
    asm("add.rn.f32x2 %0, %1, %2;" : "=l"(d) : "l"(a), "l"(b));
    return d;
}
__device__ __forceinline__ float2 unpack2(unsigned long long a) {
    float2 f;
    asm("mov.b64 {%0, %1}, %2;" : "=f"(f.x), "=f"(f.y) : "l"(a));
    return f;
}

// ---------------------------------------------------------------------------
// Precompute: warp = one state k, lane = dim d. shfl-reduce the constants.
// Launch <<<2, 1024>>> (two blocks of 32 warps cover k=0..63).
// ---------------------------------------------------------------------------
__global__ void precompute_kernel(const float* __restrict__ means,
                                  const float* __restrict__ covars) {
    int w = threadIdx.x >> 5;
    int d = threadIdx.x & 31;
    int k = blockIdx.x * 32 + w;
    if (k >= KK) return;
    float c = covars[k * DD + d];
    float m = means [k * DD + d];
    float ic = 1.0f / c;
    g_pp[k * DD + d] = make_float2(-0.5f * ic, m * ic);
    float m2 = m * m * ic;
    float lc = logf(c);
    #pragma unroll
    for (int off = 16; off; off >>= 1) {
        m2 += __shfl_xor_sync(0xffffffffu, m2, off);
        lc += __shfl_xor_sync(0xffffffffu, lc, off);
    }
    if (d == 0) g_base[k] = -0.5f * (m2 + lc + (float)DD * LOG2PI);
}

// ---------------------------------------------------------------------------
// Emission kernel: fully parallel over (t,s). Block = 64 threads (one per k),
// tile of A_TILE consecutive (t,s) pairs. xx holds (x^2, x) pairs so each d
// costs exactly one FFMA2 against the (ninv, miv) parameter pair.
// Output layout [s][t][k] so the recursion kernel streams contiguously in t.
// ---------------------------------------------------------------------------
__global__ __launch_bounds__(64) void emission_kernel(const float* __restrict__ data) {
    const int k = threadIdx.x;
    const int tile = blockIdx.x;                      // TS / A_TILE blocks
    __shared__ __align__(16) float2 xx[A_TILE][DD];   // (x*x, x)

    // Parameter pairs for this state into registers (u64 = packed float2)
    unsigned long long pp[DD];
    {
        const ulonglong2* p2 = reinterpret_cast<const ulonglong2*>(&g_pp[k * DD]);
        #pragma unroll
        for (int i = 0; i < DD / 2; i++) {
            ulonglong2 v = p2[i];
            pp[2 * i] = v.x; pp[2 * i + 1] = v.y;
        }
    }
    const float base = g_base[k];

    // Cooperative coalesced load of the tile; build (x^2, x) pairs.
    const float* src = data + (size_t)tile * A_TILE * DD;
    #pragma unroll
    for (int i = 0; i < (A_TILE * DD) / 64; i++) {
        int idx = i * 64 + k;
        float x = src[idx];
        xx[idx >> 5][idx & 31] = make_float2(x * x, x);
    }
    __syncthreads();

    const int ts0 = tile * A_TILE;
    #pragma unroll 2
    for (int j = 0; j < A_TILE; j++) {
        const ulonglong2* xr = reinterpret_cast<const ulonglong2*>(xx[j]);
        unsigned long long a0 = 0ull, a1 = 0ull, a2 = 0ull, a3 = 0ull;
        #pragma unroll
        for (int i = 0; i < 16; i += 2) {         // 32 FFMA2 = 64 FMA
            ulonglong2 v0 = xr[i];
            ulonglong2 v1 = xr[i + 1];
            a0 = ffma2(v0.x, pp[2 * i + 0], a0);
            a1 = ffma2(v0.y, pp[2 * i + 1], a1);
            a2 = ffma2(v1.x, pp[2 * i + 2], a2);
            a3 = ffma2(v1.y, pp[2 * i + 3], a3);
        }
        float2 f = unpack2(fadd2(fadd2(a0, a1), fadd2(a2, a3)));
        float p = __expf(base + f.x + f.y);
        int ts = ts0 + j;                         // data is [t][s][d]: s fastest
        int t = ts >> 9;                          // / SS
        int s = ts & (SS - 1);
        g_probs[((size_t)s * TT + t) * KK + k] = p;
    }
}

// ---------------------------------------------------------------------------
// Forward recursion: one block per sequence, one thread per state.
// Per step: 32 FFMA2 transition dot over shared alpha (read as register-pair
// f32x2 operands, zero packing cost), emission prob from depth-8 prefetch
// ring, reduction deferred one step (warp shfl tree runs in the slack).
// ---------------------------------------------------------------------------
__global__ __launch_bounds__(KK) void hmm_forward_kernel(
    const float* __restrict__ initp,
    const float* __restrict__ A,
    float* __restrict__ out)
{
    const int s = blockIdx.x;
    const int k = threadIdx.x;

    __shared__ __align__(16) float acc_sh[2][KK];
    __shared__ float red_sh[2][2];

    // A column for state k, packed in j-pairs: Ac[j] = (A[2j][k], A[2j+1][k])
    unsigned long long Ac[KK / 2];
    #pragma unroll
    for (int j = 0; j < KK / 2; j++) {
        float2 f = make_float2(__ldg(&A[(2 * j) * KK + k]),
                               __ldg(&A[(2 * j + 1) * KK + k]));
        unsigned long long u; memcpy(&u, &f, 8);
        Ac[j] = u;
    }
    const float initk = __ldg(&initp[k]);
    const float* pk = g_probs + (size_t)s * TT * KK + k;

    // Prefetch ring: slot t&7 holds p_t. Prologue loads t=1..8.
    float pr[8];
    #pragma unroll
    for (int i = 1; i <= 8; i++) pr[i & 7] = __ldg(pk + (size_t)i * KK);
    float p0 = __ldg(pk);

    float logden = 0.0f;

    // ---- t = 0 ----
    float acc = initk * p0;
    acc_sh[0][k] = acc;
    {
        float v = acc;
        #pragma unroll
        for (int off = 16; off; off >>= 1)
            v += __shfl_xor_sync(0xffffffffu, v, off);
        if ((k & 31) == 0) red_sh[0][k >> 5] = v;
    }
    __syncthreads();

    // ---- t = 1 .. TT-1 (unroll 8 so ring index t&7 is static) ----
    for (int tb = 1; tb < TT; tb += 8) {
        #pragma unroll
        for (int i = 0; i < 8; i++) {
            const int t = tb + i;
            if (t < TT) {                        // uniform across block
                const int cb = t & 1, pb = cb ^ 1;
                float p = pr[t & 7];
                if (t + 8 < TT) pr[t & 7] = __ldg(pk + (size_t)(t + 8) * KK);

                // dsum_{t-1}: shuffle tree finished last step.
                float dsum = red_sh[pb][0] + red_sh[pb][1];
                float r = __frcp_rn(dsum);
                if (k == 0) logden += __logf(dsum);

                // Transition dot: 32 FFMA2 over broadcast LDS.128 operands.
                const ulonglong2* a2 = reinterpret_cast<const ulonglong2*>(acc_sh[pb]);
                unsigned long long q0 = 0ull, q1 = 0ull, q2 = 0ull, q3 = 0ull;
                #pragma unroll
                for (int jj = 0; jj < 16; jj += 2) {
                    ulonglong2 v0 = a2[jj];
                    ulonglong2 v1 = a2[jj + 1];
                    q0 = ffma2(v0.x, Ac[2 * jj + 0], q0);
                    q1 = ffma2(v0.y, Ac[2 * jj + 1], q1);
                    q2 = ffma2(v1.x, Ac[2 * jj + 2], q2);
                    q3 = ffma2(v1.y, Ac[2 * jj + 3], q3);
                }
                float2 f = unpack2(fadd2(fadd2(q0, q1), fadd2(q2, q3)));
                // Rescale to O(1) BEFORE multiplying by p (underflow-safe).
                float dotn = (f.x + f.y) * r;
                acc = p * dotn;
                acc_sh[cb][k] = acc;

                // Start reduction of dsum_t (consumed next step).
                float w = acc;
                #pragma unroll
                for (int off = 16; off; off >>= 1)
                    w += __shfl_xor_sync(0xffffffffu, w, off);
                if ((k & 31) == 0) red_sh[cb][k >> 5] = w;

                __syncthreads();
            }
        }
    }

    // Epilogue: final normalization
    {
        float dsum = red_sh[(TT - 1) & 1][0] + red_sh[(TT - 1) & 1][1];
        float r = __frcp_rn(dsum);
        out[(size_t)s * KK + k] = acc * r;
        if (k == 0) {
            logden += __logf(dsum);
            g_logden[s] = logden;
        }
    }
}

// ---------------------------------------------------------------------------
// Deterministic reduction of per-sequence log-denominators -> -log_likelihood
// ---------------------------------------------------------------------------
__global__ void finalize_kernel(float* __restrict__ out, int out_size) {
    __shared__ float sh[SS];
    int tid = threadIdx.x;
    sh[tid] = g_logden[tid];
    __syncthreads();
    #pragma unroll
    for (int off = SS / 2; off > 0; off >>= 1) {
        if (tid < off) sh[tid] += sh[tid + off];
        __syncthreads();
    }
    if (tid == 0 && out_size > SS * KK) {
        out[out_size - 1] = -sh[0];
    }
}

extern "C" void kernel_launch(void* const* d_in, const int* in_sizes, int n_in,
                              void* d_out, int out_size) {
    const float* data  = (const float*)d_in[0];  // [T,S,D]
    const float* initp = (const float*)d_in[1];  // [K]
    const float* A     = (const float*)d_in[2];  // [K,K]
    const float* means = (const float*)d_in[3];  // [K,D]
    const float* covar = (const float*)d_in[4];  // [K,D]
    float* out = (float*)d_out;

    precompute_kernel<<<2, 1024>>>(means, covar);
    emission_kernel<<<(TT * SS) / A_TILE, 64>>>(data);
    hmm_forward_kernel<<<SS, KK>>>(initp, A, out);
    finalize_kernel<<<1, SS>>>(out, out_size);
}

// round 12
// speedup vs baseline: 1.3954x; 1.3954x over previous
#include <cuda_runtime.h>
#include <cuda_bf16.h>
#include <math.h>
#include <string.h>

// Problem constants (fixed by the dataset)
#define TT 1024
#define SS 512
#define DD 32
#define KK 64
#define LOG2PI 1.8378770664093453f

// Device-global scratch (no allocations allowed)
__device__ float2 g_pp[KK * DD];        // (-0.5/covar, mean/covar) packed pairs
__device__ float  g_base[KK];           // log-density constant per state
__device__ float  g_dsum[SS * TT];      // per-step denominators
__device__ float  g_logden[SS];         // per-sequence sum log(denom)

// ---- packed fp32x2 helpers (sm_103a) --------------------------------------
__device__ __forceinline__ unsigned long long ffma2(unsigned long long a,
                                                    unsigned long long b,
                                                    unsigned long long c) {
    unsigned long long d;
    asm("fma.rn.f32x2 %0, %1, %2, %3;" : "=l"(d) : "l"(a), "l"(b), "l"(c));
    return d;
}
__device__ __forceinline__ unsigned long long fadd2(unsigned long long a,
                                                    unsigned long long b) {
    unsigned long long d;
    asm("add.rn.f32x2 %0, %1, %2;" : "=l"(d) : "l"(a), "l"(b));
    return d;
}
__device__ __forceinline__ float2 unpack2(unsigned long long a) {
    float2 f;
    asm("mov.b64 {%0, %1}, %2;" : "=f"(f.x), "=f"(f.y) : "l"(a));
    return f;
}

// ---------------------------------------------------------------------------
// Precompute: warp = one state k, lane = dim d. shfl-reduce the constants.
// ---------------------------------------------------------------------------
__global__ void precompute_kernel(const float* __restrict__ means,
                                  const float* __restrict__ covars) {
    int w = threadIdx.x >> 5;
    int d = threadIdx.x & 31;
    int k = blockIdx.x * 32 + w;
    if (k >= KK) return;
    float c = covars[k * DD + d];
    float m = means [k * DD + d];
    float ic = 1.0f / c;
    g_pp[k * DD + d] = make_float2(-0.5f * ic, m * ic);
    float m2 = m * m * ic;
    float lc = logf(c);
    #pragma unroll
    for (int off = 16; off; off >>= 1) {
        m2 += __shfl_xor_sync(0xffffffffu, m2, off);
        lc += __shfl_xor_sync(0xffffffffu, lc, off);
    }
    if (d == 0) g_base[k] = -0.5f * (m2 + lc + (float)DD * LOG2PI);
}

// ---------------------------------------------------------------------------
// Fused forward kernel (R6 structure): one block per sequence, one thread
// per state. Per step, ONE __syncthreads:
//   - emission: 32 FFMA2 over shared (x^2, x) pairs vs packed param regs
//   - transition: 32 FFMA2 over shared alpha pairs vs packed A-column regs
//   - normalization deferred one step; dsum reduction (shfl tree) runs in the
//     slack of the next step's dot product
//   - dsum stored to global scratch; NO logf on the serial path
//   - ordering acc = p * (dot * rcp(dsum)) is underflow-safe
// ---------------------------------------------------------------------------
__global__ __launch_bounds__(KK) void hmm_forward_kernel(
    const float* __restrict__ data,      // [T, S, D]
    const float* __restrict__ initp,     // [K]
    const float* __restrict__ A,         // [K, K]
    float* __restrict__ out)             // [S, K]
{
    const int s = blockIdx.x;
    const int k = threadIdx.x;

    __shared__ __align__(16) float  acc_sh[2][KK];  // unnormalized alpha
    __shared__ __align__(16) float2 xsh[2][DD];     // (x^2, x) ring
    __shared__ float red_sh[2][2];                  // warp partial sums

    // Packed emission params for state k: pp[d] = (-0.5/c_d, m_d/c_d)
    unsigned long long pp[DD];
    {
        const ulonglong2* p2 = reinterpret_cast<const ulonglong2*>(&g_pp[k * DD]);
        #pragma unroll
        for (int i = 0; i < DD / 2; i++) {
            ulonglong2 v = p2[i];
            pp[2 * i] = v.x; pp[2 * i + 1] = v.y;
        }
    }
    const float base  = g_base[k];
    const float initk = __ldg(&initp[k]);

    // Packed A column: Ac[j] = (A[2j][k], A[2j+1][k])
    unsigned long long Ac[KK / 2];
    #pragma unroll
    for (int j = 0; j < KK / 2; j++) {
        float2 f = make_float2(__ldg(&A[(2 * j) * KK + k]),
                               __ldg(&A[(2 * j + 1) * KK + k]));
        unsigned long long u; memcpy(&u, &f, 8);
        Ac[j] = u;
    }

    // Prologue: stage (x^2, x) for t=0,1 into shared; x(2) in register
    const float* dptr = data + (size_t)s * DD;   // data[(t*S+s)*D + d]
    float xnext = 0.0f;
    if (k < DD) {
        float x0 = __ldg(dptr + k);
        float x1 = __ldg(dptr + (size_t)1 * SS * DD + k);
        xsh[0][k] = make_float2(x0 * x0, x0);
        xsh[1][k] = make_float2(x1 * x1, x1);
        xnext     = __ldg(dptr + (size_t)2 * SS * DD + k);
    }
    __syncthreads();

    // Emission for current buffer: logp = base + sum_d (x^2,x).(ninv,miv)
    auto emission = [&](int buf) -> float {
        const ulonglong2* xr = reinterpret_cast<const ulonglong2*>(xsh[buf]);
        unsigned long long a0 = 0ull, a1 = 0ull, a2 = 0ull, a3 = 0ull;
        #pragma unroll
        for (int i = 0; i < DD / 4; i += 2) {        // 32 FFMA2 total
            ulonglong2 v0 = xr[2 * i];
            ulonglong2 v1 = xr[2 * i + 1];
            ulonglong2 v2 = xr[2 * i + 2];
            ulonglong2 v3 = xr[2 * i + 3];
            a0 = ffma2(v0.x, pp[4 * i + 0], a0);
            a1 = ffma2(v0.y, pp[4 * i + 1], a1);
            a2 = ffma2(v1.x, pp[4 * i + 2], a2);
            a3 = ffma2(v1.y, pp[4 * i + 3], a3);
            a0 = ffma2(v2.x, pp[4 * i + 4], a0);
            a1 = ffma2(v2.y, pp[4 * i + 5], a1);
            a2 = ffma2(v3.x, pp[4 * i + 6], a2);
            a3 = ffma2(v3.y, pp[4 * i + 7], a3);
        }
        float2 f = unpack2(fadd2(fadd2(a0, a1), fadd2(a2, a3)));
        return __expf(base + f.x + f.y);
    };

    // ---- t = 0 ----
    float acc = initk * emission(0);
    acc_sh[0][k] = acc;
    {
        float v = acc;
        #pragma unroll
        for (int off = 16; off; off >>= 1)
            v += __shfl_xor_sync(0xffffffffu, v, off);
        if ((k & 31) == 0) red_sh[0][k >> 5] = v;
    }
    __syncthreads();

    float* dsum_out = g_dsum + (size_t)s * TT;

    // ---- t = 1 .. TT-1 ----
    for (int t = 1; t < TT; t++) {
        const int cb = t & 1;
        const int pb = cb ^ 1;

        // Stage (x^2, x) for t+1; issue load for t+2
        if (k < DD) {
            if (t + 1 < TT) xsh[pb][k] = make_float2(xnext * xnext, xnext);
            if (t + 2 < TT)
                xnext = __ldg(dptr + (size_t)(t + 2) * SS * DD + k);
        }

        // dsum_{t-1}: shuffle tree finished last step; combine + store.
        float dsum = red_sh[pb][0] + red_sh[pb][1];
        float r = __frcp_rn(dsum);
        if (k == 0) dsum_out[t - 1] = dsum;     // fire-and-forget

        // Transition dot: 32 FFMA2 over broadcast LDS.128 alpha pairs
        const ulonglong2* a2p = reinterpret_cast<const ulonglong2*>(acc_sh[pb]);
        unsigned long long q0 = 0ull, q1 = 0ull, q2 = 0ull, q3 = 0ull;
        #pragma unroll
        for (int jj = 0; jj < 16; jj += 2) {
            ulonglong2 v0 = a2p[jj];
            ulonglong2 v1 = a2p[jj + 1];
            q0 = ffma2(v0.x, Ac[2 * jj + 0], q0);
            q1 = ffma2(v0.y, Ac[2 * jj + 1], q1);
            q2 = ffma2(v1.x, Ac[2 * jj + 2], q2);
            q3 = ffma2(v1.y, Ac[2 * jj + 3], q3);
        }
        float2 f = unpack2(fadd2(fadd2(q0, q1), fadd2(q2, q3)));
        float dotn = (f.x + f.y) * r;           // rescale BEFORE p (underflow-safe)

        float p = emission(cb);
        acc = p * dotn;
        acc_sh[cb][k] = acc;

        // Start reduction of dsum_t (consumed next step)
        float w = acc;
        #pragma unroll
        for (int off = 16; off; off >>= 1)
            w += __shfl_xor_sync(0xffffffffu, w, off);
        if ((k & 31) == 0) red_sh[cb][k >> 5] = w;

        __syncthreads();
    }

    // Epilogue
    {
        float dsum = red_sh[(TT - 1) & 1][0] + red_sh[(TT - 1) & 1][1];
        float r = __frcp_rn(dsum);
        out[(size_t)s * KK + k] = acc * r;
        if (k == 0) dsum_out[TT - 1] = dsum;
    }
}

// ---------------------------------------------------------------------------
// Parallel log-sum over t: one block per sequence, fixed-order tree reduce.
// ---------------------------------------------------------------------------
__global__ void logsum_kernel() {
    __shared__ float sh[256];
    const int s = blockIdx.x;
    const int tid = threadIdx.x;
    const float* ds = g_dsum + (size_t)s * TT;
    float acc = 0.0f;
    #pragma unroll
    for (int i = 0; i < TT / 256; i++)
        acc += __logf(ds[i * 256 + tid]);
    sh[tid] = acc;
    __syncthreads();
    #pragma unroll
    for (int off = 128; off > 0; off >>= 1) {
        if (tid < off) sh[tid] += sh[tid + off];
        __syncthreads();
    }
    if (tid == 0) g_logden[s] = sh[0];
}

// ---------------------------------------------------------------------------
// Deterministic reduction over sequences -> -log_likelihood
// ---------------------------------------------------------------------------
__global__ void finalize_kernel(float* __restrict__ out, int out_size) {
    __shared__ float sh[SS];
    int tid = threadIdx.x;
    sh[tid] = g_logden[tid];
    __syncthreads();
    #pragma unroll
    for (int off = SS / 2; off > 0; off >>= 1) {
        if (tid < off) sh[tid] += sh[tid + off];
        __syncthreads();
    }
    if (tid == 0 && out_size > SS * KK) {
        out[out_size - 1] = -sh[0];
    }
}

extern "C" void kernel_launch(void* const* d_in, const int* in_sizes, int n_in,
                              void* d_out, int out_size) {
    const float* data  = (const float*)d_in[0];  // [T,S,D]
    const float* initp = (const float*)d_in[1];  // [K]
    const float* A     = (const float*)d_in[2];  // [K,K]
    const float* means = (const float*)d_in[3];  // [K,D]
    const float* covar = (const float*)d_in[4];  // [K,D]
    float* out = (float*)d_out;

    precompute_kernel<<<2, 1024>>>(means, covar);
    hmm_forward_kernel<<<SS, KK>>>(data, initp, A, out);
    logsum_kernel<<<SS, 256>>>();
    finalize_kernel<<<1, SS>>>(out, out_size);
}

// round 13
// speedup vs baseline: 1.6186x; 1.1600x over previous
#include <cuda_runtime.h>
#include <cuda_bf16.h>
#include <math.h>
#include <string.h>

// Problem constants (fixed by the dataset)
#define TT 1024
#define SS 512
#define DD 32
#define KK 64
#define LOG2PI 1.8378770664093453f

// Device-global scratch (no allocations allowed)
__device__ float2 g_pp[KK * DD];        // (-0.5/covar, mean/covar) packed pairs
__device__ float  g_base[KK];           // log-density constant per state
__device__ float  g_dsum[SS * TT];      // per-step denominators
__device__ float  g_logden[SS];         // per-sequence sum log(denom)

// ---- packed fp32x2 helpers (sm_103a) --------------------------------------
__device__ __forceinline__ unsigned long long ffma2(unsigned long long a,
                                                    unsigned long long b,
                                                    unsigned long long c) {
    unsigned long long d;
    asm("fma.rn.f32x2 %0, %1, %2, %3;" : "=l"(d) : "l"(a), "l"(b), "l"(c));
    return d;
}
__device__ __forceinline__ unsigned long long fadd2(unsigned long long a,
                                                    unsigned long long b) {
    unsigned long long d;
    asm("add.rn.f32x2 %0, %1, %2;" : "=l"(d) : "l"(a), "l"(b));
    return d;
}
__device__ __forceinline__ float2 unpack2(unsigned long long a) {
    float2 f;
    asm("mov.b64 {%0, %1}, %2;" : "=f"(f.x), "=f"(f.y) : "l"(a));
    return f;
}

// ---------------------------------------------------------------------------
// Precompute: warp = one state k, lane = dim d. shfl-reduce the constants.
// ---------------------------------------------------------------------------
__global__ void precompute_kernel(const float* __restrict__ means,
                                  const float* __restrict__ covars) {
    int w = threadIdx.x >> 5;
    int d = threadIdx.x & 31;
    int k = blockIdx.x * 32 + w;
    if (k >= KK) return;
    float c = covars[k * DD + d];
    float m = means [k * DD + d];
    float ic = 1.0f / c;
    g_pp[k * DD + d] = make_float2(-0.5f * ic, m * ic);
    float m2 = m * m * ic;
    float lc = logf(c);
    #pragma unroll
    for (int off = 16; off; off >>= 1) {
        m2 += __shfl_xor_sync(0xffffffffu, m2, off);
        lc += __shfl_xor_sync(0xffffffffu, lc, off);
    }
    if (d == 0) g_base[k] = -0.5f * (m2 + lc + (float)DD * LOG2PI);
}

// ---------------------------------------------------------------------------
// Fused forward kernel: one block per sequence, one thread per state.
// Per step, ONE __syncthreads and NO reduction tree:
//   - dsum_{t-1} computed by EVERY thread from the same shared alpha operands
//     the transition dot already loads (32 piggyback fadd2, overlaps the dot)
//   - x staging/prefetch split across BOTH warps (16 dims each) -> no skew
//   - normalization ordering acc = p * (dot * rcp(dsum)) is underflow-safe
//   - dsum stored to global scratch; logf done later in a parallel kernel
// ---------------------------------------------------------------------------
__global__ __launch_bounds__(KK) void hmm_forward_kernel(
    const float* __restrict__ data,      // [T, S, D]
    const float* __restrict__ initp,     // [K]
    const float* __restrict__ A,         // [K, K]
    float* __restrict__ out)             // [S, K]
{
    const int s = blockIdx.x;
    const int k = threadIdx.x;
    const int lane = k & 31;
    const int wrp  = k >> 5;

    __shared__ __align__(16) float  acc_sh[2][KK];  // unnormalized alpha
    __shared__ __align__(16) float2 xsh[2][DD];     // (x^2, x) ring
    __shared__ float red_sh[2];                     // epilogue only

    // Packed emission params for state k: pp[d] = (-0.5/c_d, m_d/c_d)
    unsigned long long pp[DD];
    {
        const ulonglong2* p2 = reinterpret_cast<const ulonglong2*>(&g_pp[k * DD]);
        #pragma unroll
        for (int i = 0; i < DD / 2; i++) {
            ulonglong2 v = p2[i];
            pp[2 * i] = v.x; pp[2 * i + 1] = v.y;
        }
    }
    const float base  = g_base[k];
    const float initk = __ldg(&initp[k]);

    // Packed A column: Ac[j] = (A[2j][k], A[2j+1][k])
    unsigned long long Ac[KK / 2];
    #pragma unroll
    for (int j = 0; j < KK / 2; j++) {
        float2 f = make_float2(__ldg(&A[(2 * j) * KK + k]),
                               __ldg(&A[(2 * j + 1) * KK + k]));
        unsigned long long u; memcpy(&u, &f, 8);
        Ac[j] = u;
    }

    // x staging: both warps participate, 16 dims each (kills barrier skew)
    const bool stager = (lane < 16);
    const int  d_my   = wrp * 16 + lane;            // valid when stager
    const float* dptr = data + (size_t)s * DD;      // data[(t*S+s)*D + d]
    float xn = 0.0f;
    if (stager) {
        float x0 = __ldg(dptr + d_my);
        float x1 = __ldg(dptr + (size_t)1 * SS * DD + d_my);
        xsh[0][d_my] = make_float2(x0 * x0, x0);
        xsh[1][d_my] = make_float2(x1 * x1, x1);
        xn           = __ldg(dptr + (size_t)2 * SS * DD + d_my);
    }
    __syncthreads();

    // Emission: logp = base + sum_d (x^2,x).(ninv,miv); 32 FFMA2
    auto emission = [&](int buf) -> float {
        const ulonglong2* xr = reinterpret_cast<const ulonglong2*>(xsh[buf]);
        unsigned long long a0 = 0ull, a1 = 0ull, a2 = 0ull, a3 = 0ull;
        #pragma unroll
        for (int i = 0; i < DD / 4; i += 2) {
            ulonglong2 v0 = xr[2 * i];
            ulonglong2 v1 = xr[2 * i + 1];
            ulonglong2 v2 = xr[2 * i + 2];
            ulonglong2 v3 = xr[2 * i + 3];
            a0 = ffma2(v0.x, pp[4 * i + 0], a0);
            a1 = ffma2(v0.y, pp[4 * i + 1], a1);
            a2 = ffma2(v1.x, pp[4 * i + 2], a2);
            a3 = ffma2(v1.y, pp[4 * i + 3], a3);
            a0 = ffma2(v2.x, pp[4 * i + 4], a0);
            a1 = ffma2(v2.y, pp[4 * i + 5], a1);
            a2 = ffma2(v3.x, pp[4 * i + 6], a2);
            a3 = ffma2(v3.y, pp[4 * i + 7], a3);
        }
        float2 f = unpack2(fadd2(fadd2(a0, a1), fadd2(a2, a3)));
        return __expf(base + f.x + f.y);
    };

    // ---- t = 0 ---- (no reduction needed: dsum_0 computed in step 1)
    float acc = initk * emission(0);
    acc_sh[0][k] = acc;
    __syncthreads();

    float* dsum_out = g_dsum + (size_t)s * TT;

    // ---- t = 1 .. TT-1 ----
    #pragma unroll 2
    for (int t = 1; t < TT; t++) {
        const int cb = t & 1;
        const int pb = cb ^ 1;

        // Stage (x^2, x) for t+1; issue load for t+2
        if (stager) {
            if (t + 1 < TT) xsh[pb][d_my] = make_float2(xn * xn, xn);
            if (t + 2 < TT)
                xn = __ldg(dptr + (size_t)(t + 2) * SS * DD + d_my);
        }

        // Transition dot (32 FFMA2) + piggyback dsum (32 fadd2) over the SAME
        // broadcast LDS.128 operands. dsum_{t-1} needs no cross-thread tree.
        const ulonglong2* a2p = reinterpret_cast<const ulonglong2*>(acc_sh[pb]);
        unsigned long long q0 = 0ull, q1 = 0ull, q2 = 0ull, q3 = 0ull;
        unsigned long long u0 = 0ull, u1 = 0ull, u2 = 0ull, u3 = 0ull;
        #pragma unroll
        for (int jj = 0; jj < 16; jj += 2) {
            ulonglong2 v0 = a2p[jj];
            ulonglong2 v1 = a2p[jj + 1];
            q0 = ffma2(v0.x, Ac[2 * jj + 0], q0);
            q1 = ffma2(v0.y, Ac[2 * jj + 1], q1);
            q2 = ffma2(v1.x, Ac[2 * jj + 2], q2);
            q3 = ffma2(v1.y, Ac[2 * jj + 3], q3);
            u0 = fadd2(u0, v0.x);
            u1 = fadd2(u1, v0.y);
            u2 = fadd2(u2, v1.x);
            u3 = fadd2(u3, v1.y);
        }
        float2 fq = unpack2(fadd2(fadd2(q0, q1), fadd2(q2, q3)));
        float2 fu = unpack2(fadd2(fadd2(u0, u1), fadd2(u2, u3)));
        float dsum = fu.x + fu.y;
        float r = __frcp_rn(dsum);
        if (k == 0) dsum_out[t - 1] = dsum;     // fire-and-forget

        float dotn = (fq.x + fq.y) * r;         // rescale BEFORE p (underflow-safe)
        float p = emission(cb);
        acc = p * dotn;
        acc_sh[cb][k] = acc;

        __syncthreads();
    }

    // Epilogue: one reduction tree for dsum_{TT-1}, then final normalization
    {
        float v = acc;
        #pragma unroll
        for (int off = 16; off; off >>= 1)
            v += __shfl_xor_sync(0xffffffffu, v, off);
        if (lane == 0) red_sh[wrp] = v;
        __syncthreads();
        float dsum = red_sh[0] + red_sh[1];
        float r = __frcp_rn(dsum);
        out[(size_t)s * KK + k] = acc * r;
        if (k == 0) dsum_out[TT - 1] = dsum;
    }
}

// ---------------------------------------------------------------------------
// Parallel log-sum over t: one block per sequence, fixed-order tree reduce.
// ---------------------------------------------------------------------------
__global__ void logsum_kernel() {
    __shared__ float sh[256];
    const int s = blockIdx.x;
    const int tid = threadIdx.x;
    const float* ds = g_dsum + (size_t)s * TT;
    float acc = 0.0f;
    #pragma unroll
    for (int i = 0; i < TT / 256; i++)
        acc += __logf(ds[i * 256 + tid]);
    sh[tid] = acc;
    __syncthreads();
    #pragma unroll
    for (int off = 128; off > 0; off >>= 1) {
        if (tid < off) sh[tid] += sh[tid + off];
        __syncthreads();
    }
    if (tid == 0) g_logden[s] = sh[0];
}

// ---------------------------------------------------------------------------
// Deterministic reduction over sequences -> -log_likelihood
// ---------------------------------------------------------------------------
__global__ void finalize_kernel(float* __restrict__ out, int out_size) {
    __shared__ float sh[SS];
    int tid = threadIdx.x;
    sh[tid] = g_logden[tid];
    __syncthreads();
    #pragma unroll
    for (int off = SS / 2; off > 0; off >>= 1) {
        if (tid < off) sh[tid] += sh[tid + off];
        __syncthreads();
    }
    if (tid == 0 && out_size > SS * KK) {
        out[out_size - 1] = -sh[0];
    }
}

extern "C" void kernel_launch(void* const* d_in, const int* in_sizes, int n_in,
                              void* d_out, int out_size) {
    const float* data  = (const float*)d_in[0];  // [T,S,D]
    const float* initp = (const float*)d_in[1];  // [K]
    const float* A     = (const float*)d_in[2];  // [K,K]
    const float* means = (const float*)d_in[3];  // [K,D]
    const float* covar = (const float*)d_in[4];  // [K,D]
    float* out = (float*)d_out;

    precompute_kernel<<<2, 1024>>>(means, covar);
    hmm_forward_kernel<<<SS, KK>>>(data, initp, A, out);
    logsum_kernel<<<SS, 256>>>();
    finalize_kernel<<<1, SS>>>(out, out_size);
}